// round 1
// baseline (speedup 1.0000x reference)
#include <cuda_runtime.h>
#include <cuda_bf16.h>
#include <cstdint>
#include <math.h>

// Problem constants
#define BATCH 4
#define SLEN  4096
#define DMODEL 512
#define SK    512          // number of strided keys (SLEN / 8)

// Scratch (allocation-free rule: __device__ globals)
__device__ float g_scores[(size_t)BATCH * SLEN * SK];  // 33.5 MB
__device__ float g_probs [(size_t)BATCH * SLEN * SK];  // 33.5 MB

// ---------------------------------------------------------------------------
// TF32 helpers (3xTF32 split for fp32-accurate tensor-core GEMM)
// ---------------------------------------------------------------------------
__device__ __forceinline__ uint32_t f2tf32(float x) {
    uint32_t r;
    asm("cvt.rna.tf32.f32 %0, %1;" : "=r"(r) : "f"(x));
    return r;
}

__device__ __forceinline__ void split_tf32(float x, uint32_t& hi, uint32_t& lo) {
    hi = f2tf32(x);
    float hf = __uint_as_float(hi);
    lo = f2tf32(x - hf);
}

__device__ __forceinline__ void mma_tf32(float* c, const uint32_t* a, const uint32_t* b) {
    asm volatile(
        "mma.sync.aligned.m16n8k8.row.col.f32.tf32.tf32.f32 "
        "{%0,%1,%2,%3}, {%4,%5,%6,%7}, {%8,%9}, {%0,%1,%2,%3};\n"
        : "+f"(c[0]), "+f"(c[1]), "+f"(c[2]), "+f"(c[3])
        : "r"(a[0]), "r"(a[1]), "r"(a[2]), "r"(a[3]), "r"(b[0]), "r"(b[1]));
}

// ---------------------------------------------------------------------------
// Kernel 1: mask region.  mask[i][j] = (j % 8 == 0) && (j <= i), as 1.0/0.0
// ---------------------------------------------------------------------------
__global__ __launch_bounds__(256) void mask_kernel(float* __restrict__ mout) {
    int i = blockIdx.x;
    float4* m4 = (float4*)(mout + (size_t)i * SLEN);
    #pragma unroll
    for (int kk = 0; kk < 4; ++kk) {
        int g = threadIdx.x + kk * 256;           // float4 index 0..1023, j0 = 4g
        float x = (((g & 1) == 0) && (4 * g <= i)) ? 1.0f : 0.0f;
        m4[g] = make_float4(x, 0.0f, 0.0f, 0.0f);
    }
}

// ---------------------------------------------------------------------------
// GEMM tiling constants
// ---------------------------------------------------------------------------
#define BM 128
#define BN 128
#define BK 16
#define APAD 20      // smem row stride (floats) for [128 x 16] tiles  -> conflict-free frags
#define VPAD 136     // smem row stride (floats) for [16 x 128] V tile -> conflict-free frags

// ---------------------------------------------------------------------------
// Kernel 2: scores = (scale*Q) @ K_strided^T   (3xTF32)
// grid (nj=4, mi=32, b=4); skip tiles fully above the strided-causal frontier
// ---------------------------------------------------------------------------
__global__ __launch_bounds__(256) void gemm_qk(const float* __restrict__ q,
                                               const float* __restrict__ kmat) {
    const int nj = blockIdx.x, mi = blockIdx.y, b = blockIdx.z;
    if (128 * nj > 16 * mi + 15) return;   // no query in this m-tile can see these keys

    __shared__ float As[BM * APAD];
    __shared__ float Bs[BN * APAD];

    const int tid  = threadIdx.x;
    const int warp = tid >> 5, lane = tid & 31;
    const int wm = warp >> 1, wn = warp & 1;       // 4x2 warp grid -> warp tile 32(m) x 64(n)
    const int g  = lane >> 2, t4 = lane & 3;

    const float scale = 0.0441941738241592f;       // 1/sqrt(512)

    float acc[2][8][4] = {};

    for (int kc = 0; kc < DMODEL / BK; ++kc) {
        // load A tile [128 x 16] of Q (pre-scaled)
        #pragma unroll
        for (int s = 0; s < 2; ++s) {
            int slot = tid + s * 256;              // 0..511 float4 slots
            int r = slot >> 2, c4 = slot & 3;
            const float4 vA = *(const float4*)(q +
                ((size_t)(b * SLEN + mi * BM + r)) * DMODEL + kc * BK + c4 * 4);
            float* dst = &As[r * APAD + c4 * 4];
            dst[0] = vA.x * scale; dst[1] = vA.y * scale;
            dst[2] = vA.z * scale; dst[3] = vA.w * scale;
        }
        // load B tile [128 x 16] of strided K rows (j = 8t)
        #pragma unroll
        for (int s = 0; s < 2; ++s) {
            int slot = tid + s * 256;
            int r = slot >> 2, c4 = slot & 3;
            const float4 vB = *(const float4*)(kmat +
                ((size_t)(b * SLEN + 8 * (nj * BN + r))) * DMODEL + kc * BK + c4 * 4);
            float* dst = &Bs[r * APAD + c4 * 4];
            dst[0] = vB.x; dst[1] = vB.y; dst[2] = vB.z; dst[3] = vB.w;
        }
        __syncthreads();

        #pragma unroll
        for (int kkk = 0; kkk < BK; kkk += 8) {
            uint32_t ah[2][4], al[2][4];
            #pragma unroll
            for (int m2 = 0; m2 < 2; ++m2) {
                int r0 = wm * 32 + m2 * 16 + g;
                split_tf32(As[r0 * APAD + kkk + t4],          ah[m2][0], al[m2][0]);
                split_tf32(As[(r0 + 8) * APAD + kkk + t4],    ah[m2][1], al[m2][1]);
                split_tf32(As[r0 * APAD + kkk + t4 + 4],      ah[m2][2], al[m2][2]);
                split_tf32(As[(r0 + 8) * APAD + kkk + t4 + 4],ah[m2][3], al[m2][3]);
            }
            #pragma unroll
            for (int n2 = 0; n2 < 8; ++n2) {
                int n = wn * 64 + n2 * 8 + g;
                uint32_t bh[2], bl[2];
                split_tf32(Bs[n * APAD + kkk + t4],     bh[0], bl[0]);
                split_tf32(Bs[n * APAD + kkk + t4 + 4], bh[1], bl[1]);
                #pragma unroll
                for (int m2 = 0; m2 < 2; ++m2) {
                    mma_tf32(acc[m2][n2], ah[m2], bh);
                    mma_tf32(acc[m2][n2], ah[m2], bl);
                    mma_tf32(acc[m2][n2], al[m2], bh);
                }
            }
        }
        __syncthreads();
    }

    float* outb = g_scores + (size_t)b * SLEN * SK;
    #pragma unroll
    for (int m2 = 0; m2 < 2; ++m2) {
        int r0 = mi * BM + wm * 32 + m2 * 16 + g;
        #pragma unroll
        for (int n2 = 0; n2 < 8; ++n2) {
            int c0 = nj * BN + wn * 64 + n2 * 8 + 2 * t4;
            *(float2*)(outb + (size_t)r0 * SK + c0)       = make_float2(acc[m2][n2][0], acc[m2][n2][1]);
            *(float2*)(outb + (size_t)(r0 + 8) * SK + c0) = make_float2(acc[m2][n2][2], acc[m2][n2][3]);
        }
    }
}

// ---------------------------------------------------------------------------
// Kernel 3: per-row masked softmax over 512 strided scores.
// Writes compact probs P to scratch AND the full dense 4096-wide weight row.
// One block (128 threads) per (b,i) row; thread owns t = 4*tid .. 4*tid+3.
// ---------------------------------------------------------------------------
__global__ __launch_bounds__(128) void softmax_kernel(float* __restrict__ wout) {
    const int row = blockIdx.x;                     // 0..16383 (= b*4096 + i)
    const int i   = row & (SLEN - 1);
    const int tid = threadIdx.x;
    const int tmax = i >> 3;                        // largest valid t
    const int t0 = tid * 4;

    const float4 s4 = *((const float4*)(g_scores + (size_t)row * SK) + tid);
    float s[4] = {s4.x, s4.y, s4.z, s4.w};

    float m = -INFINITY;
    #pragma unroll
    for (int j = 0; j < 4; ++j)
        if (t0 + j <= tmax) m = fmaxf(m, s[j]);

    __shared__ float redm[4];
    #pragma unroll
    for (int off = 16; off; off >>= 1) m = fmaxf(m, __shfl_xor_sync(0xffffffffu, m, off));
    if ((tid & 31) == 0) redm[tid >> 5] = m;
    __syncthreads();
    m = fmaxf(fmaxf(redm[0], redm[1]), fmaxf(redm[2], redm[3]));

    float e[4];
    float sum = 0.0f;
    #pragma unroll
    for (int j = 0; j < 4; ++j) {
        e[j] = (t0 + j <= tmax) ? expf(s[j] - m) : 0.0f;
        sum += e[j];
    }
    __shared__ float reds[4];
    #pragma unroll
    for (int off = 16; off; off >>= 1) sum += __shfl_xor_sync(0xffffffffu, sum, off);
    if ((tid & 31) == 0) reds[tid >> 5] = sum;
    __syncthreads();
    sum = reds[0] + reds[1] + reds[2] + reds[3];

    const float inv = 1.0f / sum;
    float p[4];
    #pragma unroll
    for (int j = 0; j < 4; ++j) p[j] = e[j] * inv;

    // compact probs for the PV GEMM
    *((float4*)(g_probs + (size_t)row * SK) + tid) = make_float4(p[0], p[1], p[2], p[3]);

    // dense attn_weights row: j = 8t carries p[t], everything else 0.
    // thread writes float4s g = 8*tid .. 8*tid+7 ; even g -> lane0 = p[(g/2) mod 4]
    float4* w4 = (float4*)(wout + (size_t)row * SLEN) + tid * 8;
    #pragma unroll
    for (int gg = 0; gg < 8; ++gg) {
        float x = (gg & 1) ? 0.0f : p[gg >> 1];
        w4[gg] = make_float4(x, 0.0f, 0.0f, 0.0f);
    }
}

// ---------------------------------------------------------------------------
// Kernel 4: output = P @ V_strided   (3xTF32), k-loop truncated by causality
// grid (dj=4, mi=32, b=4)
// ---------------------------------------------------------------------------
__global__ __launch_bounds__(256) void gemm_pv(const float* __restrict__ v,
                                               float* __restrict__ outO) {
    const int dj = blockIdx.x, mi = blockIdx.y, b = blockIdx.z;

    __shared__ float As[BM * APAD];
    __shared__ float Vs[16 * VPAD];

    const int tid  = threadIdx.x;
    const int warp = tid >> 5, lane = tid & 31;
    const int wm = warp >> 1, wn = warp & 1;
    const int g  = lane >> 2, t4 = lane & 3;

    float acc[2][8][4] = {};

    const int nchunks = mi + 1;   // t only goes up to 16*mi+15 for this query tile

    for (int kc = 0; kc < nchunks; ++kc) {
        // load A tile [128 x 16] of P
        #pragma unroll
        for (int s = 0; s < 2; ++s) {
            int slot = tid + s * 256;
            int r = slot >> 2, c4 = slot & 3;
            const float4 vA = *(const float4*)(g_probs +
                ((size_t)(b * SLEN + mi * BM + r)) * SK + kc * BK + c4 * 4);
            float* dst = &As[r * APAD + c4 * 4];
            dst[0] = vA.x; dst[1] = vA.y; dst[2] = vA.z; dst[3] = vA.w;
        }
        // load V tile [16 t x 128 d] (strided rows j = 8t)
        #pragma unroll
        for (int s = 0; s < 2; ++s) {
            int slot = tid + s * 256;                  // 512 float4 slots
            int tr = slot >> 5, c4 = slot & 31;        // tr 0..15, c4 0..31
            const float4 vV = *(const float4*)(v +
                ((size_t)(b * SLEN + 8 * (kc * 16 + tr))) * DMODEL + dj * 128 + c4 * 4);
            float* dst = &Vs[tr * VPAD + c4 * 4];
            dst[0] = vV.x; dst[1] = vV.y; dst[2] = vV.z; dst[3] = vV.w;
        }
        __syncthreads();

        #pragma unroll
        for (int kkk = 0; kkk < BK; kkk += 8) {
            uint32_t ah[2][4], al[2][4];
            #pragma unroll
            for (int m2 = 0; m2 < 2; ++m2) {
                int r0 = wm * 32 + m2 * 16 + g;
                split_tf32(As[r0 * APAD + kkk + t4],           ah[m2][0], al[m2][0]);
                split_tf32(As[(r0 + 8) * APAD + kkk + t4],     ah[m2][1], al[m2][1]);
                split_tf32(As[r0 * APAD + kkk + t4 + 4],       ah[m2][2], al[m2][2]);
                split_tf32(As[(r0 + 8) * APAD + kkk + t4 + 4], ah[m2][3], al[m2][3]);
            }
            #pragma unroll
            for (int n2 = 0; n2 < 8; ++n2) {
                int n = wn * 64 + n2 * 8 + g;              // d index within the 128 tile
                uint32_t bh[2], bl[2];
                split_tf32(Vs[(kkk + t4) * VPAD + n],     bh[0], bl[0]);
                split_tf32(Vs[(kkk + t4 + 4) * VPAD + n], bh[1], bl[1]);
                #pragma unroll
                for (int m2 = 0; m2 < 2; ++m2) {
                    mma_tf32(acc[m2][n2], ah[m2], bh);
                    mma_tf32(acc[m2][n2], ah[m2], bl);
                    mma_tf32(acc[m2][n2], al[m2], bh);
                }
            }
        }
        __syncthreads();
    }

    #pragma unroll
    for (int m2 = 0; m2 < 2; ++m2) {
        int r0 = mi * BM + wm * 32 + m2 * 16 + g;
        #pragma unroll
        for (int n2 = 0; n2 < 8; ++n2) {
            int c0 = dj * 128 + wn * 64 + n2 * 8 + 2 * t4;
            *(float2*)(outO + ((size_t)(b * SLEN + r0)) * DMODEL + c0) =
                make_float2(acc[m2][n2][0], acc[m2][n2][1]);
            *(float2*)(outO + ((size_t)(b * SLEN + r0 + 8)) * DMODEL + c0) =
                make_float2(acc[m2][n2][2], acc[m2][n2][3]);
        }
    }
}

// ---------------------------------------------------------------------------
// Launch: out layout = [output (B*S*D)] [attn_weights (B*S*S)] [mask (S*S)]
// ---------------------------------------------------------------------------
extern "C" void kernel_launch(void* const* d_in, const int* in_sizes, int n_in,
                              void* d_out, int out_size) {
    const float* q = (const float*)d_in[0];
    const float* k = (const float*)d_in[1];
    const float* v = (const float*)d_in[2];

    float* o_out = (float*)d_out;
    float* w_out = o_out + (size_t)BATCH * SLEN * DMODEL;
    float* m_out = w_out + (size_t)BATCH * SLEN * SLEN;

    mask_kernel   <<<SLEN, 256>>>(m_out);
    gemm_qk       <<<dim3(4, 32, BATCH), 256>>>(q, k);
    softmax_kernel<<<BATCH * SLEN, 128>>>(w_out);
    gemm_pv       <<<dim3(4, 32, BATCH), 256>>>(v, o_out);
}